// round 16
// baseline (speedup 1.0000x reference)
#include <cuda_runtime.h>
#include <cuda_bf16.h>
#include <cstdint>
#include <cstring>

#define DD 1024
#define MM 256
#define BB 2048
#define NCH 8          // 8 chunks x 128 d
#define XSTG 1024      // uint4 per x stage (64 rows x 16)
#define CSTG 2112      // uint4 per c stage (64 rows x 33, odd stride)

// Device scratch (no allocations allowed)
__device__ __align__(16) uint32_t g_cb[MM * DD];          // per d-pair: {c1 bf16x2, c0 bf16x2}
__device__ __align__(16) uint32_t g_xb[BB * (DD / 2)];    // x as bf16x2 pairs
__device__ __align__(16) float g_logw[MM];
__device__ __align__(16) float g_comp[BB * MM];           // sum over d of log2(2*lik)

__device__ __forceinline__ __nv_bfloat162 asbf2(uint32_t u) {
    __nv_bfloat162 r; memcpy(&r, &u, 4); return r;
}
__device__ __forceinline__ uint32_t asu32(__nv_bfloat162 b) {
    uint32_t u; memcpy(&u, &b, 4); return u;
}
__device__ __forceinline__ void cp16(uint32_t dst, const void* src) {
    asm volatile("cp.async.ca.shared.global [%0], [%1], 16;" :: "r"(dst), "l"(src));
}
__device__ __forceinline__ uint32_t packbf(float a, float b) {
    return asu32(__floats2bfloat162_rn(a, b));
}

// ---------------------------------------------------------------------------
// Fused prep, high-TLP R3 shape: blocks [0,2048) x->bf16 (1 float4/thread);
// [2048,2560) P->coefs (1 float2/thread); block 2560: logw.
// ---------------------------------------------------------------------------
__global__ void prep_kernel(const float* __restrict__ x,
                            const float* __restrict__ P,
                            const float* __restrict__ W) {
    int bk = blockIdx.x, t = threadIdx.x;
    if (bk < 2048) {
        int idx = bk * 256 + t;                   // one per 4 d of x
        float4 v = reinterpret_cast<const float4*>(x)[idx];
        uint2 w;
        w.x = packbf(v.x, v.y);
        w.y = packbf(v.z, v.w);
        reinterpret_cast<uint2*>(g_xb)[idx] = w;
    } else if (bk < 2560) {
        int idx = (bk - 2048) * 256 + t;          // one per d-pair of P
        float2 pv = reinterpret_cast<const float2*>(P)[idx];
        float c0a = 2.0f / (1.0f + __expf(pv.x)); // 2*(1-p)
        float c0b = 2.0f / (1.0f + __expf(pv.y));
        float c1a = 2.0f - 2.0f * c0a;            // 2*(2p-1)
        float c1b = 2.0f - 2.0f * c0b;
        uint2 w;
        w.x = packbf(c1a, c1b);
        w.y = packbf(c0a, c0b);
        reinterpret_cast<uint2*>(g_cb)[idx] = w;
    } else {
        __shared__ float sh[MM];
        float w = W[t];
        sh[t] = w;
        __syncthreads();
        for (int s = MM / 2; s > 0; s >>= 1) {
            if (t < s) sh[t] = fmaxf(sh[t], sh[t + s]);
            __syncthreads();
        }
        float mx = sh[0];
        __syncthreads();
        sh[t] = expf(w - mx);
        __syncthreads();
        for (int s = MM / 2; s > 0; s >>= 1) {
            if (t < s) sh[t] += sh[t + s];
            __syncthreads();
        }
        g_logw[t] = w - (mx + logf(sh[0]));
    }
}

// ---------------------------------------------------------------------------
// Main (R8, frozen structure): block 64b x 64m, 512 threads = 16(tx,m) x
// 16(ty,b) x 2(tz,d-split), thread tile 4b x 4m over half of each 128-d
// chunk. 3-stage cp.async ring, ONE __syncthreads per chunk. bf16
// HFMA2/HMUL2 inner; prod initialized from jq=0 product (exact vs mul-by-1);
// __log2f merge per chunk (64 d per accumulator).
// ---------------------------------------------------------------------------
__global__ void __launch_bounds__(512, 1) main_kernel() {
    extern __shared__ uint4 sm[];
    uint4* xs = sm;                // 3 stages x XSTG
    uint4* cs = sm + 3 * XSTG;     // 3 stages x CSTG

    const int t  = threadIdx.x;
    const int tx = t & 15;
    const int ty = (t >> 4) & 15;
    const int tz = t >> 8;
    const int bBase = blockIdx.x * 64;
    const int mBase = blockIdx.y * 64;

    const int xr = t >> 3, xq = t & 7;
    const uint32_t* xsrc = g_xb + (size_t)(bBase + xr) * (DD / 2) + xq * 4;
    const uint32_t* csrc = g_cb + (size_t)(mBase + xr) * DD + xq * 4;
    const uint32_t xd = (uint32_t)__cvta_generic_to_shared(&xs[xr * 16 + xq]);
    const uint32_t cd = (uint32_t)__cvta_generic_to_shared(&cs[xr * 33 + xq]);

    auto issue = [&](int ck, int slot) {
        const uint32_t* xp = xsrc + ck * 64;
        uint32_t xb = xd + slot * XSTG * 16;
        cp16(xb,          xp);
        cp16(xb + 8 * 16, xp + 32);
        const uint32_t* cp = csrc + ck * 128;
        uint32_t cb = cd + slot * CSTG * 16;
        cp16(cb,           cp);
        cp16(cb + 8 * 16,  cp + 32);
        cp16(cb + 16 * 16, cp + 64);
        cp16(cb + 24 * 16, cp + 96);
        asm volatile("cp.async.commit_group;");
    };

    issue(0, 0);
    issue(1, 1);

    float acc[4][4];
#pragma unroll
    for (int i = 0; i < 4; i++)
#pragma unroll
        for (int jm = 0; jm < 4; jm++) acc[i][jm] = 0.0f;

    for (int ck = 0; ck < NCH; ck++) {
        asm volatile("cp.async.wait_group 1;");
        __syncthreads();
        if (ck + 2 < NCH) issue(ck + 2, (ck + 2) % 3);
        else asm volatile("cp.async.commit_group;");

        const int slot = ck % 3;
        const uint4* xb = xs + slot * XSTG + ty * 16 + tz * 8;
        const uint4* cb = cs + slot * CSTG + tx * 33 + tz * 16;

        __nv_bfloat162 prod[4][4];

#pragma unroll
        for (int jq = 0; jq < 8; jq++) {          // 8 d per jq (per tz half)
            uint4 xv[4];
#pragma unroll
            for (int i = 0; i < 4; i++) xv[i] = xb[i * 16 * 16 + jq];
#pragma unroll
            for (int jm = 0; jm < 4; jm++) {
                uint4 c0 = cb[jm * 16 * 33 + jq * 2];
                uint4 c1 = cb[jm * 16 * 33 + jq * 2 + 1];
#pragma unroll
                for (int i = 0; i < 4; i++) {
                    __nv_bfloat162 l0 = __hfma2(asbf2(c0.x), asbf2(xv[i].x), asbf2(c0.y));
                    __nv_bfloat162 l1 = __hfma2(asbf2(c0.z), asbf2(xv[i].y), asbf2(c0.w));
                    __nv_bfloat162 l2 = __hfma2(asbf2(c1.x), asbf2(xv[i].z), asbf2(c1.y));
                    __nv_bfloat162 l3 = __hfma2(asbf2(c1.z), asbf2(xv[i].w), asbf2(c1.w));
                    __nv_bfloat162 m = __hmul2(__hmul2(l0, l1), __hmul2(l2, l3));
                    prod[i][jm] = (jq == 0) ? m : __hmul2(prod[i][jm], m);
                }
            }
        }
        // merge: 64 d per accumulator (scaled x2: safe fp32 range)
#pragma unroll
        for (int i = 0; i < 4; i++)
#pragma unroll
            for (int jm = 0; jm < 4; jm++) {
                uint32_t u = asu32(prod[i][jm]);
                float hi = __uint_as_float(u & 0xFFFF0000u);
                float lo = __uint_as_float(u << 16);
                acc[i][jm] += __log2f(hi * lo);
            }
    }

    asm volatile("cp.async.wait_group 0;");
    __syncthreads();
    // combine tz halves through smem (stride 17 floats: no bank conflicts)
    float* sh = (float*)sm;
    const int tid256 = t & 255;
    if (tz == 1) {
#pragma unroll
        for (int i = 0; i < 4; i++)
#pragma unroll
            for (int jm = 0; jm < 4; jm++)
                sh[tid256 * 17 + i * 4 + jm] = acc[i][jm];
    }
    __syncthreads();
    if (tz == 0) {
#pragma unroll
        for (int i = 0; i < 4; i++)
#pragma unroll
            for (int jm = 0; jm < 4; jm++) {
                float a = acc[i][jm] + sh[tid256 * 17 + i * 4 + jm];
                g_comp[(size_t)(bBase + ty + 16 * i) * MM + (mBase + tx + 16 * jm)] = a;
            }
    }
}

// ---------------------------------------------------------------------------
// Reduce: one warp per batch. comp_ll = (acc2 - 1024)*ln2 + logw, then
// logsumexp over 256 components.
// ---------------------------------------------------------------------------
__global__ void reduce_kernel(float* __restrict__ out) {
    const float LN2 = 0.69314718055994531f;
    int w = (blockIdx.x << 4) + (threadIdx.x >> 5);
    int lane = threadIdx.x & 31;
    const float4* cp4 = reinterpret_cast<const float4*>(g_comp + (size_t)w * MM) + lane * 2;
    const float4* lw4 = reinterpret_cast<const float4*>(g_logw) + lane * 2;
    float v[8];
    float mx = -1e30f;
#pragma unroll
    for (int k = 0; k < 2; k++) {
        float4 c = cp4[k];
        float4 l = lw4[k];
        v[k*4+0] = (c.x - 1024.0f) * LN2 + l.x;
        v[k*4+1] = (c.y - 1024.0f) * LN2 + l.y;
        v[k*4+2] = (c.z - 1024.0f) * LN2 + l.z;
        v[k*4+3] = (c.w - 1024.0f) * LN2 + l.w;
#pragma unroll
        for (int j = 0; j < 4; j++) mx = fmaxf(mx, v[k*4+j]);
    }
#pragma unroll
    for (int o = 16; o > 0; o >>= 1) mx = fmaxf(mx, __shfl_xor_sync(0xFFFFFFFFu, mx, o));
    float s = 0.0f;
#pragma unroll
    for (int k = 0; k < 8; k++) s += __expf(v[k] - mx);
#pragma unroll
    for (int o = 16; o > 0; o >>= 1) s += __shfl_xor_sync(0xFFFFFFFFu, s, o);
    if (lane == 0) out[w] = mx + __logf(s);
}

extern "C" void kernel_launch(void* const* d_in, const int* in_sizes, int n_in,
                              void* d_out, int out_size) {
    const float* x = nullptr;
    const float* W = nullptr;
    const float* P = nullptr;
    for (int i = 0; i < n_in; i++) {
        if      (in_sizes[i] == BB * DD) x = (const float*)d_in[i];
        else if (in_sizes[i] == MM)      W = (const float*)d_in[i];
        else if (in_sizes[i] == MM * DD) P = (const float*)d_in[i];
    }

    prep_kernel<<<2561, 256>>>(x, P, W);

    const int SMEM = 3 * (XSTG + CSTG) * 16;   // 150,528 bytes
    cudaFuncSetAttribute(main_kernel, cudaFuncAttributeMaxDynamicSharedMemorySize, SMEM);
    dim3 grid(BB / 64, MM / 64);
    main_kernel<<<grid, 512, SMEM>>>();

    reduce_kernel<<<BB / 16, 512>>>((float*)d_out);
}